// round 10
// baseline (speedup 1.0000x reference)
#include <cuda_runtime.h>
#include <cuda_fp16.h>
#include <math.h>
#include <stdint.h>

#define LIN   32
#define LOUT  32
#define BSZ   64
#define EMB   256
#define DENC  256
#define DD    512
#define VOUT  32000
#define NG5   2560   // 5*D
#define NG4   1024   // 4*DENC

// ===================== helpers =====================
__device__ __forceinline__ uint32_t smem_u32(const void* p){
    uint32_t a;
    asm("{ .reg .u64 t; cvta.to.shared.u64 t, %1; cvt.u32.u64 %0, t; }" : "=r"(a) : "l"(p));
    return a;
}
__device__ __forceinline__ void ldmx4(uint32_t& r0, uint32_t& r1, uint32_t& r2, uint32_t& r3, uint32_t addr){
    asm volatile("ldmatrix.sync.aligned.m8n8.x4.shared.b16 {%0,%1,%2,%3}, [%4];"
        : "=r"(r0), "=r"(r1), "=r"(r2), "=r"(r3) : "r"(addr));
}
__device__ __forceinline__ void mma16816(float* c, uint32_t a0, uint32_t a1, uint32_t a2, uint32_t a3,
                                         uint32_t b0, uint32_t b1){
    asm volatile("mma.sync.aligned.m16n8k16.row.col.f32.f16.f16.f32 "
        "{%0,%1,%2,%3}, {%4,%5,%6,%7}, {%8,%9}, {%0,%1,%2,%3};"
        : "+f"(c[0]), "+f"(c[1]), "+f"(c[2]), "+f"(c[3])
        : "r"(a0), "r"(a1), "r"(a2), "r"(a3), "r"(b0), "r"(b1));
}
#define CP16(dst, src) asm volatile("cp.async.cg.shared.global [%0], [%1], 16;" :: "r"(dst), "l"(src))
#define CPCOMMIT()     asm volatile("cp.async.commit_group;" ::: "memory")
#define CPWAIT0()      asm volatile("cp.async.wait_group 0;" ::: "memory")

#define SMBUF 10240   // generic hmma kernel: bytes per smem buffer (128*40 halves)

// ===================== device scratch =====================
__device__ float  g_x_emb[LIN*BSZ*EMB];
__device__ __half g_y_embh[LOUT*BSZ*EMB];
__device__ float  g_zxe[2*LIN*BSZ*NG4];    // PERMUTED cols (perm4)
__device__ float  g_h[2*BSZ*DENC];
__device__ float  g_c[2*BSZ*DENC];
__device__ __half g_h_allh[LIN*BSZ*(2*DENC)];
__device__ float  g_zx_h[LIN*BSZ*NG5];     // PERMUTED cols (permc)
__device__ float  g_zx_y[LOUT*BSZ*NG5];    // PERMUTED cols (permc)
__device__ float  g_hor_c[LIN*BSZ*DD];
__device__ float  g_ver_c[LOUT*BSZ*DD];
__device__ __half g_hor_sh[LIN*BSZ*DD];
__device__ __half g_ver_sh[LOUT*BSZ*DD];
__device__ __half g_states_h[LOUT*BSZ*DD];
__device__ __half g_Wsh[NG5*(2*DD)];       // PERMUTED rows: [permc(n)][k=1024]
__device__ __half g_Wxh[NG5*(2*DENC+EMB)]; // PERMUTED rows: [permc(n)][k=768]
__device__ __half g_Wlogh[VOUT*DD];        // [n=32000][k=512]
__device__ float  g_bcp[NG5];              // permc-permuted b_cell

__device__ __forceinline__ float sigf(float x){ return 1.0f/(1.0f+__expf(-x)); }
__device__ __forceinline__ float tanh_e(float x){
    x = fminf(fmaxf(x, -15.f), 15.f);
    float t = __expf(2.f*x);
    return (t-1.f)/(t+1.f);
}
// gate-interleave permutations
__device__ __forceinline__ int permc(int n){ return (n & 511)*5 + (n >> 9); }   // decoder (5 gates)
__device__ __forceinline__ int perm4(int n){ return (n & 255)*4 + (n >> 8); }   // encoder (4 gates)
__device__ __forceinline__ int invperm4(int p){ return (p >> 2) + (p & 3)*256; }

// ===================== init / embed / conversions =====================
__global__ void init_zero_kernel(){
    int i = blockIdx.x*blockDim.x + threadIdx.x;
    int stride = gridDim.x*blockDim.x;
    for (int k=i; k<LIN*BSZ*DD; k+=stride){
        g_hor_c[k]=0.f; g_ver_c[k]=0.f;
        g_hor_sh[k]=__float2half(0.f); g_ver_sh[k]=__float2half(0.f);
    }
    for (int k=i; k<2*BSZ*DENC; k+=stride){ g_h[k]=0.f; g_c[k]=0.f; }
}

__global__ void embed_kernel(const int* __restrict__ x, const int* __restrict__ y,
                             const float* __restrict__ emb_in,
                             const float* __restrict__ emb_out){
    int row = blockIdx.x, e = threadIdx.x;
    g_x_emb[row*EMB+e] = emb_in[x[row]*EMB+e];
    int j = row >> 6, b = row & 63;
    int yt = (j==0) ? 1 : y[(j-1)*BSZ + b];
    g_y_embh[row*EMB+e] = __float2half(emb_out[yt*EMB+e]);
}

// tiled fp32->fp16 transpose: dst[n][k] = (half)src[k][n]
__global__ void conv_tr_kernel(const float* __restrict__ src, __half* __restrict__ dst,
                               int K, int N){
    __shared__ float t[32][33];
    int n0 = blockIdx.x*32, k0 = blockIdx.y*32;
    int tx = threadIdx.x, ty = threadIdx.y;
    for (int yy=ty; yy<32; yy+=8) t[yy][tx] = src[(size_t)(k0+yy)*N + n0+tx];
    __syncthreads();
    for (int yy=ty; yy<32; yy+=8) dst[(size_t)(n0+yy)*K + k0+tx] = __float2half(t[tx][yy]);
}
// permc-permuted variant: dst[permc(n)][k]
__global__ void conv_tr_perm_kernel(const float* __restrict__ src, __half* __restrict__ dst,
                                    int K, int N){
    __shared__ float t[32][33];
    int n0 = blockIdx.x*32, k0 = blockIdx.y*32;
    int tx = threadIdx.x, ty = threadIdx.y;
    for (int yy=ty; yy<32; yy+=8) t[yy][tx] = src[(size_t)(k0+yy)*N + n0+tx];
    __syncthreads();
    for (int yy=ty; yy<32; yy+=8) dst[(size_t)permc(n0+yy)*K + k0+tx] = __float2half(t[tx][yy]);
}
__global__ void bias_perm_kernel(const float* __restrict__ b){
    int n = blockIdx.x*256 + threadIdx.x;
    if (n < NG5) g_bcp[permc(n)] = b[n];
}

// ===================== fp32 FFMA GEMM, perm4-permuted output (encoder input projection) =====================
__global__ void __launch_bounds__(128) gemm_nt_perm4(
        const float* __restrict__ A, int lda, const float* __restrict__ Bm, int ldb,
        float* __restrict__ C, int ldc, const float* __restrict__ bias, int K){
    __shared__ float As[16][36];
    __shared__ float Bs[16][68];
    const int m0 = blockIdx.y*32, n0 = blockIdx.x*64;
    const int tid = threadIdx.x, tr = tid>>4, tc = tid&15;
    float acc[4][4];
    #pragma unroll
    for (int i=0;i<4;i++) for (int j=0;j<4;j++) acc[i][j]=0.f;
    for (int k0=0;k0<K;k0+=16){
        #pragma unroll
        for (int e=0;e<4;e++){ int idx=tid+e*128; As[idx&15][idx>>4]=A[(m0+(idx>>4))*lda+k0+(idx&15)]; }
        #pragma unroll
        for (int e=0;e<8;e++){ int idx=tid+e*128; Bs[idx&15][idx>>4]=Bm[(n0+(idx>>4))*ldb+k0+(idx&15)]; }
        __syncthreads();
        #pragma unroll
        for (int kk=0;kk<16;kk++){
            float a[4], b[4];
            #pragma unroll
            for (int i=0;i<4;i++) a[i]=As[kk][tr*4+i];
            #pragma unroll
            for (int j=0;j<4;j++) b[j]=Bs[kk][tc*4+j];
            #pragma unroll
            for (int i=0;i<4;i++) for (int j=0;j<4;j++) acc[i][j]+=a[i]*b[j];
        }
        __syncthreads();
    }
    #pragma unroll
    for (int i=0;i<4;i++){ int m=m0+tr*4+i;
        #pragma unroll
        for (int j=0;j<4;j++){ int n=n0+tc*4+j; float v=acc[i][j]; if (bias) v+=bias[n];
            C[m*ldc + perm4(n)]=v; } }
}

// ===================== fused encoder step: GEMM (perm4 cols) + gates in-register =====================
// grid (16, 2, 2), 128 threads. Each thread ends up with the 4 gates of ONE channel
// for 4 batches directly in its accumulators (thanks to perm4 ordering).
__global__ void __launch_bounds__(128) enc_step_fused(
        const float* __restrict__ Whh_f, const float* __restrict__ Whh_b, int t){
    __shared__ float As[16][36];
    __shared__ float Bs[16][68];
    const int dir = blockIdx.z;
    const int m0 = blockIdx.y*32;        // batch tile
    const int n0 = blockIdx.x*64;        // permuted col tile
    const float* A  = g_h + dir*BSZ*DENC;
    const float* Bm = dir ? Whh_b : Whh_f;
    const int tid = threadIdx.x, tr = tid>>4, tc = tid&15;
    float acc[4][4];
    #pragma unroll
    for (int i=0;i<4;i++) for (int j=0;j<4;j++) acc[i][j]=0.f;
    for (int k0=0;k0<DENC;k0+=16){
        #pragma unroll
        for (int e=0;e<4;e++){ int idx=tid+e*128; As[idx&15][idx>>4]=A[(m0+(idx>>4))*DENC+k0+(idx&15)]; }
        #pragma unroll
        for (int e=0;e<8;e++){ int idx=tid+e*128; int n=idx>>4;
            Bs[idx&15][n]=Bm[invperm4(n0+n)*DENC+k0+(idx&15)]; }
        __syncthreads();
        #pragma unroll
        for (int kk=0;kk<16;kk++){
            float a[4], b[4];
            #pragma unroll
            for (int i=0;i<4;i++) a[i]=As[kk][tr*4+i];
            #pragma unroll
            for (int j=0;j<4;j++) b[j]=Bs[kk][tc*4+j];
            #pragma unroll
            for (int i=0;i<4;i++) for (int j=0;j<4;j++) acc[i][j]+=a[i]*b[j];
        }
        __syncthreads();
    }
    // epilogue: thread owns channel u = n0/4 + tc, gates j=0..3 (i,f,g,o), batches m0+tr*4+i
    const int u = (n0>>2) + tc;
    const int tt = dir ? (LIN-1-t) : t;
    #pragma unroll
    for (int i=0;i<4;i++){
        int b = m0 + tr*4 + i;
        const float* zx = g_zxe + (size_t)(dir*LIN*BSZ + tt*BSZ + b)*NG4 + n0 + tc*4;
        float zi = acc[i][0] + zx[0];
        float zf = acc[i][1] + zx[1];
        float zg = acc[i][2] + zx[2];
        float zo = acc[i][3] + zx[3];
        int hx = dir*BSZ*DENC + b*DENC + u;
        float c = g_c[hx];
        c = sigf(zf)*c + sigf(zi)*tanh_e(zg);
        float h = sigf(zo)*tanh_e(c);
        g_c[hx]=c; g_h[hx]=h;
        g_h_allh[(tt*BSZ+b)*(2*DENC) + dir*DENC + u] = __float2half(h);
    }
}

// ===================== generic cp.async HMMA NT GEMM (zx + logits) =====================
__global__ void __launch_bounds__(256) hmma_nt_async(
        const __half* __restrict__ A, int lda,
        const __half* __restrict__ B, int ldb,
        float* __restrict__ C, size_t ldc,
        const float* __restrict__ bias, int K){
    __shared__ __align__(16) __half As[2][128*40];
    __shared__ __align__(16) __half Bs[2][128*40];
    const int m0 = blockIdx.y*128, n0 = blockIdx.x*128;
    const int tid = threadIdx.x, lane = tid&31, wid = tid>>5;
    const int warp_m = wid>>1, warp_n = wid&1;
    const uint32_t sA = smem_u32(As), sB = smem_u32(Bs);
    const int nch = K >> 5;

    float acc[2][8][4];
    #pragma unroll
    for (int mt=0;mt<2;mt++) for (int nt=0;nt<8;nt++) for (int q=0;q<4;q++) acc[mt][nt][q]=0.f;

    {
        #pragma unroll
        for (int e=0;e<2;e++){
            int sid = tid + e*256; int m = sid>>2, kc = (sid&3)*8;
            CP16(sA + (m*40+kc)*2, A + (size_t)(m0+m)*lda + kc);
            CP16(sB + (m*40+kc)*2, B + (size_t)(n0+m)*ldb + kc);
        }
        CPCOMMIT();
    }
    #pragma unroll 1
    for (int c=0; c<nch; c++){
        CPWAIT0(); __syncthreads();
        if (c+1 < nch){
            int k0 = (c+1)*32, nb = (c+1)&1;
            #pragma unroll
            for (int e=0;e<2;e++){
                int sid = tid + e*256; int m = sid>>2, kc = (sid&3)*8;
                CP16(sA + nb*SMBUF + (m*40+kc)*2, A + (size_t)(m0+m)*lda + k0+kc);
                CP16(sB + nb*SMBUF + (m*40+kc)*2, B + (size_t)(n0+m)*ldb + k0+kc);
            }
            CPCOMMIT();
        }
        const uint32_t bA = sA + (c&1)*SMBUF, bB = sB + (c&1)*SMBUF;
        #pragma unroll
        for (int ks=0; ks<2; ks++){
            uint32_t af[2][4];
            #pragma unroll
            for (int mt=0; mt<2; mt++){
                int row = warp_m*32 + mt*16 + (lane&15);
                int col = ks*16 + ((lane>>4)<<3);
                ldmx4(af[mt][0], af[mt][1], af[mt][2], af[mt][3], bA + (row*40 + col)*2);
            }
            uint32_t bf[8][2];
            #pragma unroll
            for (int ntp=0; ntp<4; ntp++){
                int n = warp_n*64 + ntp*16 + ((lane>>4)<<3) + (lane&7);
                int k = ks*16 + ((lane&8)?8:0);
                uint32_t r0,r1,r2,r3;
                ldmx4(r0, r1, r2, r3, bB + (n*40 + k)*2);
                bf[2*ntp][0]=r0; bf[2*ntp][1]=r1; bf[2*ntp+1][0]=r2; bf[2*ntp+1][1]=r3;
            }
            #pragma unroll
            for (int mt=0; mt<2; mt++)
                #pragma unroll
                for (int nt=0; nt<8; nt++)
                    mma16816(acc[mt][nt], af[mt][0], af[mt][1], af[mt][2], af[mt][3],
                             bf[nt][0], bf[nt][1]);
        }
        __syncthreads();
    }

    #pragma unroll
    for (int mt=0; mt<2; mt++){
        int r0 = warp_m*32 + mt*16 + (lane>>2);
        #pragma unroll
        for (int h8=0; h8<2; h8++){
            int m = m0 + r0 + h8*8;
            #pragma unroll
            for (int nt=0; nt<8; nt++){
                int col = n0 + warp_n*64 + nt*8 + (lane&3)*2;
                float b0 = bias ? bias[col] : 0.f;
                float b1 = bias ? bias[col+1] : 0.f;
                C[(size_t)m*ldc + col]   = acc[mt][nt][h8*2+0] + b0;
                C[(size_t)m*ldc + col+1] = acc[mt][nt][h8*2+1] + b1;
            }
        }
    }
}

// ===================== fused diagonal kernel: GEMM (N=160 permuted) + gates =====================
#define D_AB   10240            // A buffer bytes (128*40 halves)
#define D_BB   12800            // B buffer bytes (160*40 halves)
#define D_SCR_STRIDE 168        // scratch floats per row

__global__ void __launch_bounds__(256) diag_fused(int d){
    __shared__ __align__(16) char sraw[2*D_AB + 2*D_BB];   // 46080B; epilogue scratch aliases
    __half* Asm = (__half*)sraw;
    __half* Bsm = (__half*)(sraw + 2*D_AB);
    float*  scratch = (float*)sraw;                        // 64*168*4 = 43008 <= 46080

    int lo = d-31; if (lo<0) lo=0;
    int hi = d<31 ? d : 31;
    const int nc = hi-lo+1;
    const int pair = blockIdx.y;
    const int i0 = lo + pair*2;
    const int bx = blockIdx.x;
    const int n0 = bx*160;        // permuted col base; channels [bx*32, bx*32+32)
    const int uBase = bx*32;
    const int tid = threadIdx.x, lane = tid&31, wid = tid>>5;
    const int warp_m = wid>>1, warp_n = wid&1;
    const uint32_t sA = smem_u32(Asm), sB = smem_u32(Bsm);

    float acc[2][10][4];
    #pragma unroll
    for (int mt=0;mt<2;mt++) for (int nt=0;nt<10;nt++) for (int q=0;q<4;q++) acc[mt][nt][q]=0.f;

    auto a_src = [&](int m, int kk) -> const __half* {
        int i = i0 + (m>>6); if (i>hi) i = hi;
        int jj = d - i;
        int b = m&63;
        return (kk < DD) ? (g_hor_sh + (i*BSZ+b)*DD + kk)
                         : (g_ver_sh + (jj*BSZ+b)*DD + (kk-DD));
    };

    // prologue: chunk 0 -> buf 0
    {
        #pragma unroll
        for (int e=0;e<2;e++){
            int sid = tid + e*256; int m = sid>>2, kc = (sid&3)*8;
            CP16(sA + (m*40+kc)*2, a_src(m, kc));
        }
        #pragma unroll
        for (int e=0;e<3;e++){
            int sid = tid + e*256;
            if (sid < 640){
                int r = sid>>2, kc = (sid&3)*8;
                CP16(sB + (r*40+kc)*2, g_Wsh + (size_t)(n0+r)*(2*DD) + kc);
            }
        }
        CPCOMMIT();
    }
    #pragma unroll 1
    for (int c=0; c<32; c++){
        CPWAIT0(); __syncthreads();
        if (c+1 < 32){
            int k0 = (c+1)*32, nb = (c+1)&1;
            #pragma unroll
            for (int e=0;e<2;e++){
                int sid = tid + e*256; int m = sid>>2, kc = (sid&3)*8;
                CP16(sA + nb*D_AB + (m*40+kc)*2, a_src(m, k0+kc));
            }
            #pragma unroll
            for (int e=0;e<3;e++){
                int sid = tid + e*256;
                if (sid < 640){
                    int r = sid>>2, kc = (sid&3)*8;
                    CP16(sB + nb*D_BB + (r*40+kc)*2, g_Wsh + (size_t)(n0+r)*(2*DD) + k0+kc);
                }
            }
            CPCOMMIT();
        }
        const uint32_t bA = sA + (c&1)*D_AB, bB = sB + (c&1)*D_BB;
        #pragma unroll
        for (int ks=0; ks<2; ks++){
            uint32_t af[2][4];
            #pragma unroll
            for (int mt=0; mt<2; mt++){
                int row = warp_m*32 + mt*16 + (lane&15);
                int col = ks*16 + ((lane>>4)<<3);
                ldmx4(af[mt][0], af[mt][1], af[mt][2], af[mt][3], bA + (row*40 + col)*2);
            }
            uint32_t bf[10][2];
            #pragma unroll
            for (int ntp=0; ntp<5; ntp++){
                int n = warp_n*80 + ntp*16 + ((lane>>4)<<3) + (lane&7);
                int k = ks*16 + ((lane&8)?8:0);
                uint32_t r0,r1,r2,r3;
                ldmx4(r0, r1, r2, r3, bB + (n*40 + k)*2);
                bf[2*ntp][0]=r0; bf[2*ntp][1]=r1; bf[2*ntp+1][0]=r2; bf[2*ntp+1][1]=r3;
            }
            #pragma unroll
            for (int mt=0; mt<2; mt++)
                #pragma unroll
                for (int nt=0; nt<10; nt++)
                    mma16816(acc[mt][nt], af[mt][0], af[mt][1], af[mt][2], af[mt][3],
                             bf[nt][0], bf[nt][1]);
        }
        __syncthreads();
    }

    // ===== fused epilogue: z -> scratch (+zx), then gate update; two passes (one per cell) =====
    #pragma unroll 1
    for (int p=0; p<2; p++){
        const int ci = pair*2 + p;
        const bool valid = (ci < nc);
        const int i = lo + (valid ? ci : 0);
        const int jj = d - i;
        if ((warp_m>>1) == p && valid){
            #pragma unroll
            for (int mt=0; mt<2; mt++){
                #pragma unroll
                for (int h8=0; h8<2; h8++){
                    int rl = (warp_m&1)*32 + mt*16 + (lane>>2) + h8*8;   // 0..63 = batch
                    const float* zh = g_zx_h + ((size_t)i*BSZ + rl)*NG5;
                    const float* zy = g_zx_y + ((size_t)jj*BSZ + rl)*NG5;
                    #pragma unroll
                    for (int nt=0; nt<10; nt++){
                        int cl = warp_n*80 + nt*8 + (lane&3)*2;
                        int gc = n0 + cl;
                        scratch[rl*D_SCR_STRIDE + cl]   = acc[mt][nt][h8*2+0] + zh[gc]   + zy[gc];
                        scratch[rl*D_SCR_STRIDE + cl+1] = acc[mt][nt][h8*2+1] + zh[gc+1] + zy[gc+1];
                    }
                }
            }
        }
        __syncthreads();
        if (valid){
            #pragma unroll 1
            for (int it = tid; it < 2048; it += 256){
                int b = it >> 5, ul = it & 31;
                const float* zr = scratch + b*D_SCR_STRIDE + ul*5;
                float gi = sigf(zr[0]);
                float gf = sigf(zr[1]);
                float go = sigf(zr[2]);
                float gl = sigf(zr[3]);
                float gg = tanh_e(zr[4]);
                int u = uBase + ul;
                int hix = (i*BSZ+b)*DD + u;
                int vix = (jj*BSZ+b)*DD + u;
                float ch = g_hor_c[hix], cv = g_ver_c[vix];
                float cc = gf*(gl*ch + (1.f-gl)*cv) + gi*gg;
                float ss = go*tanh_e(cc);
                g_hor_c[hix]=cc; g_ver_c[vix]=cc;
                __half sh = __float2half(ss);
                g_hor_sh[hix]=sh; g_ver_sh[vix]=sh;
                if (i == LIN-1) g_states_h[(jj*BSZ+b)*DD + u] = sh;
            }
        }
        __syncthreads();
    }
}

// ===================== launch =====================
extern "C" void kernel_launch(void* const* d_in, const int* in_sizes, int n_in,
                              void* d_out, int out_size){
    const int*   x      = (const int*)  d_in[0];
    const int*   y      = (const int*)  d_in[2];
    const float* emb_in = (const float*)d_in[4];
    const float* emb_out= (const float*)d_in[5];
    const float* Wih_f  = (const float*)d_in[6];
    const float* Whh_f  = (const float*)d_in[7];
    const float* b_f    = (const float*)d_in[8];
    const float* Wih_b  = (const float*)d_in[9];
    const float* Whh_b  = (const float*)d_in[10];
    const float* b_b    = (const float*)d_in[11];
    const float* Wx     = (const float*)d_in[12];
    const float* Ws     = (const float*)d_in[13];
    const float* b_cell = (const float*)d_in[14];
    const float* W_log  = (const float*)d_in[15];
    const float* b_log  = (const float*)d_in[16];
    float* out = (float*)d_out;

    float *p_x_emb, *p_zxe, *p_zx_h, *p_zx_y, *p_bcp;
    __half *p_y_embh, *p_h_allh, *p_states_h, *p_Wxh, *p_Wlogh, *p_Wsh;
    cudaGetSymbolAddress((void**)&p_x_emb,    g_x_emb);
    cudaGetSymbolAddress((void**)&p_y_embh,   g_y_embh);
    cudaGetSymbolAddress((void**)&p_zxe,      g_zxe);
    cudaGetSymbolAddress((void**)&p_h_allh,   g_h_allh);
    cudaGetSymbolAddress((void**)&p_zx_h,     g_zx_h);
    cudaGetSymbolAddress((void**)&p_zx_y,     g_zx_y);
    cudaGetSymbolAddress((void**)&p_states_h, g_states_h);
    cudaGetSymbolAddress((void**)&p_Wsh,      g_Wsh);
    cudaGetSymbolAddress((void**)&p_Wxh,      g_Wxh);
    cudaGetSymbolAddress((void**)&p_Wlogh,    g_Wlogh);
    cudaGetSymbolAddress((void**)&p_bcp,      g_bcp);

    init_zero_kernel<<<512,256>>>();
    embed_kernel<<<LIN*BSZ,EMB>>>(x, y, emb_in, emb_out);

    // weight conversions (Ws/Wx permc-permuted; W_log plain)
    conv_tr_perm_kernel<<<dim3(NG5/32, (2*DD)/32),       dim3(32,8)>>>(Ws,    p_Wsh,   2*DD,       NG5);
    conv_tr_perm_kernel<<<dim3(NG5/32, (2*DENC+EMB)/32), dim3(32,8)>>>(Wx,    p_Wxh,   2*DENC+EMB, NG5);
    conv_tr_kernel<<<dim3(VOUT/32, DD/32),               dim3(32,8)>>>(W_log, p_Wlogh, DD,         VOUT);
    bias_perm_kernel<<<NG5/256,256>>>(b_cell);

    // zx_y = y_emb @ Wx[512:768]^T + b_cell (HMMA, permc cols)
    hmma_nt_async<<<dim3(20,16),256>>>(p_y_embh, EMB, p_Wxh + 2*DENC, 2*DENC+EMB,
                                       p_zx_y, NG5, p_bcp, EMB);

    // encoder input projections (fp32, perm4-permuted output)
    gemm_nt_perm4<<<dim3(16,64),128>>>(p_x_emb, EMB, Wih_f, EMB, p_zxe,             NG4, b_f, EMB);
    gemm_nt_perm4<<<dim3(16,64),128>>>(p_x_emb, EMB, Wih_b, EMB, p_zxe+LIN*BSZ*NG4, NG4, b_b, EMB);

    // fused encoder recurrence: ONE kernel per step (GEMM + gates)
    for (int t=0; t<LIN; t++)
        enc_step_fused<<<dim3(16,2,2),128>>>(Whh_f, Whh_b, t);

    // zx_h = h_all @ Wx[0:512]^T (HMMA, permc cols)
    hmma_nt_async<<<dim3(20,16),256>>>(p_h_allh, 2*DENC, p_Wxh, 2*DENC+EMB,
                                       p_zx_h, NG5, nullptr, 2*DENC);

    // 2D-LSTM wavefront: fused GEMM+gate, one launch per diagonal
    for (int d=0; d<LIN+LOUT-1; d++){
        int lo = d-31; if (lo<0) lo=0;
        int hi = d<31 ? d : 31;
        int nc = hi - lo + 1;
        int npair = (nc + 1) >> 1;
        diag_fused<<<dim3(16,npair),256>>>(d);
    }

    // logits (HMMA): out = states_h @ Wlogh^T + b_log
    hmma_nt_async<<<dim3(250,16),256>>>(p_states_h, DD, p_Wlogh, DD,
                                        out, VOUT, b_log, DD);
}

// round 13
// speedup vs baseline: 1.0179x; 1.0179x over previous
#include <cuda_runtime.h>
#include <cuda_fp16.h>
#include <math.h>
#include <stdint.h>

#define LIN   32
#define LOUT  32
#define BSZ   64
#define EMB   256
#define DENC  256
#define DD    512
#define VOUT  32000
#define NG5   2560   // 5*D
#define NG4   1024   // 4*DENC

// ===================== helpers =====================
__device__ __forceinline__ uint32_t smem_u32(const void* p){
    uint32_t a;
    asm("{ .reg .u64 t; cvta.to.shared.u64 t, %1; cvt.u32.u64 %0, t; }" : "=r"(a) : "l"(p));
    return a;
}
__device__ __forceinline__ void ldmx4(uint32_t& r0, uint32_t& r1, uint32_t& r2, uint32_t& r3, uint32_t addr){
    asm volatile("ldmatrix.sync.aligned.m8n8.x4.shared.b16 {%0,%1,%2,%3}, [%4];"
        : "=r"(r0), "=r"(r1), "=r"(r2), "=r"(r3) : "r"(addr));
}
__device__ __forceinline__ void mma16816(float* c, uint32_t a0, uint32_t a1, uint32_t a2, uint32_t a3,
                                         uint32_t b0, uint32_t b1){
    asm volatile("mma.sync.aligned.m16n8k16.row.col.f32.f16.f16.f32 "
        "{%0,%1,%2,%3}, {%4,%5,%6,%7}, {%8,%9}, {%0,%1,%2,%3};"
        : "+f"(c[0]), "+f"(c[1]), "+f"(c[2]), "+f"(c[3])
        : "r"(a0), "r"(a1), "r"(a2), "r"(a3), "r"(b0), "r"(b1));
}
#define CP16(dst, src) asm volatile("cp.async.cg.shared.global [%0], [%1], 16;" :: "r"(dst), "l"(src))
#define CPCOMMIT()     asm volatile("cp.async.commit_group;" ::: "memory")
#define CPWAIT0()      asm volatile("cp.async.wait_group 0;" ::: "memory")

// bulk TMA-style copy (sm_90 ISA, valid on sm_100 target)
#define BULKCP(dst, src, bytes, mb) \
    asm volatile("cp.async.bulk.shared::cluster.global.mbarrier::complete_tx::bytes [%0], [%1], %2, [%3];" \
        :: "r"((uint32_t)(dst)), "l"((const void*)(src)), "r"((uint32_t)(bytes)), "r"((uint32_t)(mb)) : "memory")
#define MBARRIER_INIT(mb, c)  asm volatile("mbarrier.init.shared.b64 [%0], %1;" :: "r"((uint32_t)(mb)), "r"((uint32_t)(c)) : "memory")
#define MBARRIER_EXPECT_TX(mb, tx) asm volatile("mbarrier.arrive.expect_tx.shared.b64 _, [%0], %1;" :: "r"((uint32_t)(mb)), "r"((uint32_t)(tx)) : "memory")
#define FENCE_ASYNC_SHARED()  asm volatile("fence.proxy.async.shared::cta;" ::: "memory")
#define MBARRIER_WAIT_PARITY(mb, par) do { \
    uint32_t _mb = (uint32_t)(mb); uint32_t _p = (uint32_t)(par); uint32_t _d; \
    asm volatile("{\n\t.reg .pred p;\n\tmbarrier.try_wait.parity.acquire.cta.shared::cta.b64 p, [%1], %2;\n\tselp.b32 %0, 1, 0, p;\n\t}" \
        : "=r"(_d) : "r"(_mb), "r"(_p) : "memory"); \
    if (!_d) { \
        asm volatile("{\n\t.reg .pred P1;\n\tWL_%=:\n\tmbarrier.try_wait.parity.acquire.cta.shared::cta.b64 P1, [%0], %1, 0x989680;\n\t@P1 bra.uni WD_%=;\n\tbra.uni WL_%=;\n\tWD_%=:\n\t}" \
            :: "r"(_mb), "r"(_p) : "memory"); \
    } } while(0)

#define SW128(off)   ((off) ^ (((off) >> 3) & 0x70))
#define SMBUF 10240   // generic hmma kernel buffer bytes
#define HOFF  (LIN*8*4096)    // halves per hor s-state buffer
#define VOFF  (LOUT*8*4096)   // halves per ver s-state buffer

// ===================== device scratch =====================
__device__ float  g_x_emb[LIN*BSZ*EMB];
__device__ __half g_y_embh[LOUT*BSZ*EMB];
__device__ float  g_zxe[2*LIN*BSZ*NG4];    // perm4 cols
__device__ float  g_h[2*BSZ*DENC];
__device__ float  g_c[2*BSZ*DENC];
__device__ __half g_h_allh[LIN*BSZ*(2*DENC)];
__device__ float  g_zx_h[LIN*BSZ*NG5];     // permc cols
__device__ float  g_zx_y[LOUT*BSZ*NG5];    // permc cols
__device__ float  g_hor_c[LIN*BSZ*DD];
__device__ float  g_ver_c[LOUT*BSZ*DD];
// PING-PONG BLOCKED+SW128 fp16 s-states: [buf(2)][cell][kc(8)][64 rows x 128B]
__device__ __half g_hor_sh[2*LIN*8*64*64];
__device__ __half g_ver_sh[2*LOUT*8*64*64];
// BLOCKED+SW128 logits A: [mt(16)][kc(8)][128 rows x 128B]
__device__ __half g_states_h[16*8*128*64];
// BLOCKED+SW128 Ws: [bx(16)][kc(16)][160 rows x 128B]
__device__ __half g_Wsh[16*16*160*64];
__device__ __half g_Wxh[NG5*(2*DENC+EMB)];   // plain [permc(n)][k]
// BLOCKED+SW128 Wlog: [nt(250)][kc(8)][128 rows x 128B]
__device__ __half g_Wlogh[250*8*128*64];
__device__ float  g_bcp[NG5];

__device__ __forceinline__ float sigf(float x){ return 1.0f/(1.0f+__expf(-x)); }
__device__ __forceinline__ float tanh_e(float x){
    x = fminf(fmaxf(x, -15.f), 15.f);
    float t = __expf(2.f*x);
    return (t-1.f)/(t+1.f);
}
__device__ __forceinline__ int permc(int n){ return (n & 511)*5 + (n >> 9); }
__device__ __forceinline__ int perm4(int n){ return (n & 255)*4 + (n >> 8); }
__device__ __forceinline__ int invperm4(int p){ return (p >> 2) + (p & 3)*256; }

// ===================== init / embed / conversions =====================
__global__ void init_zero_kernel(){
    int i = blockIdx.x*blockDim.x + threadIdx.x;
    int stride = gridDim.x*blockDim.x;
    for (int k=i; k<2*LIN*BSZ*DD; k+=stride){
        g_hor_sh[k]=__float2half(0.f); g_ver_sh[k]=__float2half(0.f);
    }
    for (int k=i; k<LIN*BSZ*DD; k+=stride){ g_hor_c[k]=0.f; g_ver_c[k]=0.f; }
    for (int k=i; k<2*BSZ*DENC; k+=stride){ g_h[k]=0.f; g_c[k]=0.f; }
}

__global__ void embed_kernel(const int* __restrict__ x, const int* __restrict__ y,
                             const float* __restrict__ emb_in,
                             const float* __restrict__ emb_out){
    int row = blockIdx.x, e = threadIdx.x;
    g_x_emb[row*EMB+e] = emb_in[x[row]*EMB+e];
    int j = row >> 6, b = row & 63;
    int yt = (j==0) ? 1 : y[(j-1)*BSZ + b];
    g_y_embh[row*EMB+e] = __float2half(emb_out[yt*EMB+e]);
}

// plain permc transpose for Wx: dst[permc(n)][k]
__global__ void conv_tr_perm_kernel(const float* __restrict__ src, __half* __restrict__ dst,
                                    int K, int N){
    __shared__ float t[32][33];
    int n0 = blockIdx.x*32, k0 = blockIdx.y*32;
    int tx = threadIdx.x, ty = threadIdx.y;
    for (int yy=ty; yy<32; yy+=8) t[yy][tx] = src[(size_t)(k0+yy)*N + n0+tx];
    __syncthreads();
    for (int yy=ty; yy<32; yy+=8) dst[(size_t)permc(n0+yy)*K + k0+tx] = __float2half(t[tx][yy]);
}
// Ws -> blocked+swizzled+permc
__global__ void conv_tr_ws_kernel(const float* __restrict__ src){
    __shared__ float t[32][33];
    int n0 = blockIdx.x*32, k0 = blockIdx.y*32;
    int tx = threadIdx.x, ty = threadIdx.y;
    for (int yy=ty; yy<32; yy+=8) t[yy][tx] = src[(size_t)(k0+yy)*NG5 + n0+tx];
    __syncthreads();
    for (int yy=ty; yy<32; yy+=8){
        int p = permc(n0+yy);
        int k = k0+tx;
        int bx = p/160, r = p - bx*160;
        size_t idx = (size_t)(bx*16 + (k>>6))*10240 + (SW128(r*128 + (k&63)*2)>>1);
        g_Wsh[idx] = __float2half(t[tx][yy]);
    }
}
// Wlog -> blocked+swizzled
__global__ void conv_tr_wlog_kernel(const float* __restrict__ src){
    __shared__ float t[32][33];
    int n0 = blockIdx.x*32, k0 = blockIdx.y*32;
    int tx = threadIdx.x, ty = threadIdx.y;
    for (int yy=ty; yy<32; yy+=8) t[yy][tx] = src[(size_t)(k0+yy)*VOUT + n0+tx];
    __syncthreads();
    for (int yy=ty; yy<32; yy+=8){
        int n = n0+yy, k = k0+tx;
        int nt = n>>7, r = n&127;
        size_t idx = (size_t)(nt*8 + (k>>6))*8192 + (SW128(r*128 + (k&63)*2)>>1);
        g_Wlogh[idx] = __float2half(t[tx][yy]);
    }
}
__global__ void bias_perm_kernel(const float* __restrict__ b){
    int n = blockIdx.x*256 + threadIdx.x;
    if (n < NG5) g_bcp[permc(n)] = b[n];
}

// ===================== fp32 FFMA GEMM, perm4 output (encoder input projection) =====================
__global__ void __launch_bounds__(128) gemm_nt_perm4(
        const float* __restrict__ A, int lda, const float* __restrict__ Bm, int ldb,
        float* __restrict__ C, int ldc, const float* __restrict__ bias, int K){
    __shared__ float As[16][36];
    __shared__ float Bs[16][68];
    const int m0 = blockIdx.y*32, n0 = blockIdx.x*64;
    const int tid = threadIdx.x, tr = tid>>4, tc = tid&15;
    float acc[4][4];
    #pragma unroll
    for (int i=0;i<4;i++) for (int j=0;j<4;j++) acc[i][j]=0.f;
    for (int k0=0;k0<K;k0+=16){
        #pragma unroll
        for (int e=0;e<4;e++){ int idx=tid+e*128; As[idx&15][idx>>4]=A[(m0+(idx>>4))*lda+k0+(idx&15)]; }
        #pragma unroll
        for (int e=0;e<8;e++){ int idx=tid+e*128; Bs[idx&15][idx>>4]=Bm[(n0+(idx>>4))*ldb+k0+(idx&15)]; }
        __syncthreads();
        #pragma unroll
        for (int kk=0;kk<16;kk++){
            float a[4], b[4];
            #pragma unroll
            for (int i=0;i<4;i++) a[i]=As[kk][tr*4+i];
            #pragma unroll
            for (int j=0;j<4;j++) b[j]=Bs[kk][tc*4+j];
            #pragma unroll
            for (int i=0;i<4;i++) for (int j=0;j<4;j++) acc[i][j]+=a[i]*b[j];
        }
        __syncthreads();
    }
    #pragma unroll
    for (int i=0;i<4;i++){ int m=m0+tr*4+i;
        #pragma unroll
        for (int j=0;j<4;j++){ int n=n0+tc*4+j; float v=acc[i][j]; if (bias) v+=bias[n];
            C[m*ldc + perm4(n)]=v; } }
}

// ===================== fused encoder step =====================
__global__ void __launch_bounds__(128) enc_step_fused(
        const float* __restrict__ Whh_f, const float* __restrict__ Whh_b, int t){
    __shared__ float As[16][36];
    __shared__ float Bs[16][68];
    const int dir = blockIdx.z;
    const int m0 = blockIdx.y*32;
    const int n0 = blockIdx.x*64;
    const float* A  = g_h + dir*BSZ*DENC;
    const float* Bm = dir ? Whh_b : Whh_f;
    const int tid = threadIdx.x, tr = tid>>4, tc = tid&15;
    float acc[4][4];
    #pragma unroll
    for (int i=0;i<4;i++) for (int j=0;j<4;j++) acc[i][j]=0.f;
    for (int k0=0;k0<DENC;k0+=16){
        #pragma unroll
        for (int e=0;e<4;e++){ int idx=tid+e*128; As[idx&15][idx>>4]=A[(m0+(idx>>4))*DENC+k0+(idx&15)]; }
        #pragma unroll
        for (int e=0;e<8;e++){ int idx=tid+e*128; int n=idx>>4;
            Bs[idx&15][n]=Bm[invperm4(n0+n)*DENC+k0+(idx&15)]; }
        __syncthreads();
        #pragma unroll
        for (int kk=0;kk<16;kk++){
            float a[4], b[4];
            #pragma unroll
            for (int i=0;i<4;i++) a[i]=As[kk][tr*4+i];
            #pragma unroll
            for (int j=0;j<4;j++) b[j]=Bs[kk][tc*4+j];
            #pragma unroll
            for (int i=0;i<4;i++) for (int j=0;j<4;j++) acc[i][j]+=a[i]*b[j];
        }
        __syncthreads();
    }
    const int u = (n0>>2) + tc;
    const int tt = dir ? (LIN-1-t) : t;
    #pragma unroll
    for (int i=0;i<4;i++){
        int b = m0 + tr*4 + i;
        const float* zx = g_zxe + (size_t)(dir*LIN*BSZ + tt*BSZ + b)*NG4 + n0 + tc*4;
        float zi = acc[i][0] + zx[0];
        float zf = acc[i][1] + zx[1];
        float zg = acc[i][2] + zx[2];
        float zo = acc[i][3] + zx[3];
        int hx = dir*BSZ*DENC + b*DENC + u;
        float c = g_c[hx];
        c = sigf(zf)*c + sigf(zi)*tanh_e(zg);
        float h = sigf(zo)*tanh_e(c);
        g_c[hx]=c; g_h[hx]=h;
        g_h_allh[(tt*BSZ+b)*(2*DENC) + dir*DENC + u] = __float2half(h);
    }
}

// ===================== generic cp.async HMMA NT GEMM (zx only) =====================
__global__ void __launch_bounds__(256) hmma_nt_async(
        const __half* __restrict__ A, int lda,
        const __half* __restrict__ B, int ldb,
        float* __restrict__ C, size_t ldc,
        const float* __restrict__ bias, int K){
    __shared__ __align__(16) __half As[2][128*40];
    __shared__ __align__(16) __half Bs[2][128*40];
    const int m0 = blockIdx.y*128, n0 = blockIdx.x*128;
    const int tid = threadIdx.x, lane = tid&31, wid = tid>>5;
    const int warp_m = wid>>1, warp_n = wid&1;
    const uint32_t sA = smem_u32(As), sB = smem_u32(Bs);
    const int nch = K >> 5;

    float acc[2][8][4];
    #pragma unroll
    for (int mt=0;mt<2;mt++) for (int nt=0;nt<8;nt++) for (int q=0;q<4;q++) acc[mt][nt][q]=0.f;

    {
        #pragma unroll
        for (int e=0;e<2;e++){
            int sid = tid + e*256; int m = sid>>2, kc = (sid&3)*8;
            CP16(sA + (m*40+kc)*2, A + (size_t)(m0+m)*lda + kc);
            CP16(sB + (m*40+kc)*2, B + (size_t)(n0+m)*ldb + kc);
        }
        CPCOMMIT();
    }
    #pragma unroll 1
    for (int c=0; c<nch; c++){
        CPWAIT0(); __syncthreads();
        if (c+1 < nch){
            int k0 = (c+1)*32, nb = (c+1)&1;
            #pragma unroll
            for (int e=0;e<2;e++){
                int sid = tid + e*256; int m = sid>>2, kc = (sid&3)*8;
                CP16(sA + nb*SMBUF + (m*40+kc)*2, A + (size_t)(m0+m)*lda + k0+kc);
                CP16(sB + nb*SMBUF + (m*40+kc)*2, B + (size_t)(n0+m)*ldb + k0+kc);
            }
            CPCOMMIT();
        }
        const uint32_t bA = sA + (c&1)*SMBUF, bB = sB + (c&1)*SMBUF;
        #pragma unroll
        for (int ks=0; ks<2; ks++){
            uint32_t af[2][4];
            #pragma unroll
            for (int mt=0; mt<2; mt++){
                int row = warp_m*32 + mt*16 + (lane&15);
                int col = ks*16 + ((lane>>4)<<3);
                ldmx4(af[mt][0], af[mt][1], af[mt][2], af[mt][3], bA + (row*40 + col)*2);
            }
            uint32_t bf[8][2];
            #pragma unroll
            for (int ntp=0; ntp<4; ntp++){
                int n = warp_n*64 + ntp*16 + ((lane>>4)<<3) + (lane&7);
                int k = ks*16 + ((lane&8)?8:0);
                uint32_t r0,r1,r2,r3;
                ldmx4(r0, r1, r2, r3, bB + (n*40 + k)*2);
                bf[2*ntp][0]=r0; bf[2*ntp][1]=r1; bf[2*ntp+1][0]=r2; bf[2*ntp+1][1]=r3;
            }
            #pragma unroll
            for (int mt=0; mt<2; mt++)
                #pragma unroll
                for (int nt=0; nt<8; nt++)
                    mma16816(acc[mt][nt], af[mt][0], af[mt][1], af[mt][2], af[mt][3],
                             bf[nt][0], bf[nt][1]);
        }
        __syncthreads();
    }

    #pragma unroll
    for (int mt=0; mt<2; mt++){
        int r0 = warp_m*32 + mt*16 + (lane>>2);
        #pragma unroll
        for (int h8=0; h8<2; h8++){
            int m = m0 + r0 + h8*8;
            #pragma unroll
            for (int nt=0; nt<8; nt++){
                int col = n0 + warp_n*64 + nt*8 + (lane&3)*2;
                float b0 = bias ? bias[col] : 0.f;
                float b1 = bias ? bias[col+1] : 0.f;
                C[(size_t)m*ldc + col]   = acc[mt][nt][h8*2+0] + b0;
                C[(size_t)m*ldc + col+1] = acc[mt][nt][h8*2+1] + b1;
            }
        }
    }
}

// ===================== fused diagonal kernel: bulk-TMA GEMM + gates (ping-pong states) =====================
// dynamic smem: [mbar 128B][A0 16K][A1 16K][B0 20K][B1 20K] = 73856B
#define D_SMEM_TOT   73856
#define D_SCR_STRIDE 168

__global__ void __launch_bounds__(256) diag_fused(int d){
    extern __shared__ __align__(128) char smem[];
    const uint32_t sb = smem_u32(smem);
    const uint32_t mb0 = sb, mb1 = sb + 8;
    const uint32_t Abase = sb + 128;
    const uint32_t Bbase = sb + 128 + 32768;
    float* scratch = (float*)(smem + 128);

    int lo = d-31; if (lo<0) lo=0;
    int hi = d<31 ? d : 31;
    const int nc = hi-lo+1;
    const int pair = blockIdx.y;
    const int i0c = lo + pair*2;
    int i1c = i0c+1; if (i1c>hi) i1c = hi;
    const int jA0 = d - i0c, jA1 = d - i1c;
    const int bx = blockIdx.x;
    const int n0 = bx*160;
    const int uBase = bx*32;
    const int tid = threadIdx.x, lane = tid&31, wid = tid>>5;
    const int warp_m = wid>>1, warp_n = wid&1;
    // ping-pong: read buf = d&1, write buf = (d+1)&1
    const __half* hor_r = g_hor_sh + (size_t)(d&1)*HOFF;
    const __half* ver_r = g_ver_sh + (size_t)(d&1)*VOFF;
    __half* hor_w = g_hor_sh + (size_t)((d+1)&1)*HOFF;
    __half* ver_w = g_ver_sh + (size_t)((d+1)&1)*VOFF;

    if (tid==0){ MBARRIER_INIT(mb0,1); MBARRIER_INIT(mb1,1); }
    FENCE_ASYNC_SHARED();
    __syncthreads();

    float acc[2][10][4];
    #pragma unroll
    for (int mt=0;mt<2;mt++) for (int nt=0;nt<10;nt++) for (int q=0;q<4;q++) acc[mt][nt][q]=0.f;

    auto issue = [&](int chunk, int buf){
        uint32_t m_ = buf ? mb1 : mb0;
        MBARRIER_EXPECT_TX(m_, 36864u);
        BULKCP(Bbase + buf*20480, g_Wsh + (size_t)(bx*16 + chunk)*10240, 20480u, m_);
        const __half *s0, *s1;
        if (chunk < 8){
            s0 = hor_r + (size_t)(i0c*8+chunk)*4096;
            s1 = hor_r + (size_t)(i1c*8+chunk)*4096;
        } else {
            int kc = chunk-8;
            s0 = ver_r + (size_t)(jA0*8+kc)*4096;
            s1 = ver_r + (size_t)(jA1*8+kc)*4096;
        }
        uint32_t dA = Abase + buf*16384;
        BULKCP(dA,        s0, 8192u, m_);
        BULKCP(dA + 8192, s1, 8192u, m_);
    };
    if (tid==0){ issue(0,0); issue(1,1); }

    int ph0=0, ph1=0;
    #pragma unroll 1
    for (int c=0; c<16; c++){
        const int buf = c&1;
        if (buf==0){ MBARRIER_WAIT_PARITY(mb0, ph0); ph0^=1; }
        else       { MBARRIER_WAIT_PARITY(mb1, ph1); ph1^=1; }
        const uint32_t bA = Abase + buf*16384, bB = Bbase + buf*20480;
        #pragma unroll
        for (int ks=0; ks<4; ks++){
            uint32_t af[2][4];
            #pragma unroll
            for (int mt=0; mt<2; mt++){
                int row = warp_m*32 + mt*16 + (lane&15);
                int colb = (ks*16 + ((lane>>4)<<3))*2;
                ldmx4(af[mt][0], af[mt][1], af[mt][2], af[mt][3],
                      bA + (row>>6)*8192 + SW128((row&63)*128 + colb));
            }
            uint32_t bf[10][2];
            #pragma unroll
            for (int ntp=0; ntp<5; ntp++){
                int n = warp_n*80 + ntp*16 + ((lane>>4)<<3) + (lane&7);
                int kb = (ks*16 + ((lane&8)?8:0))*2;
                uint32_t r0,r1,r2,r3;
                ldmx4(r0, r1, r2, r3, bB + SW128(n*128 + kb));
                bf[2*ntp][0]=r0; bf[2*ntp][1]=r1; bf[2*ntp+1][0]=r2; bf[2*ntp+1][1]=r3;
            }
            #pragma unroll
            for (int mt=0; mt<2; mt++)
                #pragma unroll
                for (int nt=0; nt<10; nt++)
                    mma16816(acc[mt][nt], af[mt][0], af[mt][1], af[mt][2], af[mt][3],
                             bf[nt][0], bf[nt][1]);
        }
        __syncthreads();
        if (c+2 < 16 && tid==0) issue(c+2, buf);
    }

    // ===== fused epilogue: z -> scratch (+zx), gate update; two passes =====
    #pragma unroll 1
    for (int p=0; p<2; p++){
        const int ci = pair*2 + p;
        const bool valid = (ci < nc);
        const int i = lo + (valid ? ci : 0);
        const int jj = d - i;
        if ((warp_m>>1) == p && valid){
            #pragma unroll
            for (int mt=0; mt<2; mt++){
                #pragma unroll
                for (int h8=0; h8<2; h8++){
                    int rl = (warp_m&1)*32 + mt*16 + (lane>>2) + h8*8;
                    const float* zh = g_zx_h + ((size_t)i*BSZ + rl)*NG5;
                    const float* zy = g_zx_y + ((size_t)jj*BSZ + rl)*NG5;
                    #pragma unroll
                    for (int nt=0; nt<10; nt++){
                        int cl = warp_n*80 + nt*8 + (lane&3)*2;
                        int gc = n0 + cl;
                        scratch[rl*D_SCR_STRIDE + cl]   = acc[mt][nt][h8*2+0] + zh[gc]   + zy[gc];
                        scratch[rl*D_SCR_STRIDE + cl+1] = acc[mt][nt][h8*2+1] + zh[gc+1] + zy[gc+1];
                    }
                }
            }
        }
        __syncthreads();
        if (valid){
            #pragma unroll 1
            for (int it = tid; it < 2048; it += 256){
                int b = it >> 5, ul = it & 31;
                const float* zr = scratch + b*D_SCR_STRIDE + ul*5;
                float gi = sigf(zr[0]);
                float gf = sigf(zr[1]);
                float go = sigf(zr[2]);
                float gl = sigf(zr[3]);
                float gg = tanh_e(zr[4]);
                int u = uBase + ul;
                int kc = u>>6, ui = u&63;
                uint32_t swo = SW128(b*128 + ui*2) >> 1;
                int hix = (i*BSZ+b)*DD + u;
                int vix = (jj*BSZ+b)*DD + u;
                float ch = g_hor_c[hix], cv = g_ver_c[vix];
                float cc = gf*(gl*ch + (1.f-gl)*cv) + gi*gg;
                float ss = go*tanh_e(cc);
                g_hor_c[hix]=cc; g_ver_c[vix]=cc;
                __half sh = __float2half(ss);
                hor_w[(size_t)(i*8+kc)*4096 + swo]  = sh;
                ver_w[(size_t)(jj*8+kc)*4096 + swo] = sh;
                if (i == LIN-1){
                    int mt = jj>>1, r = ((jj&1)<<6) + b;
                    g_states_h[(size_t)(mt*8+kc)*8192 + (SW128(r*128 + ui*2)>>1)] = sh;
                }
            }
        }
        __syncthreads();
    }
}

// ===================== bulk-TMA logits GEMM =====================
// dynamic smem: [mbar 128][A0 16K][A1 16K][B0 16K][B1 16K] = 65664
#define L_SMEM_TOT 65664

__global__ void __launch_bounds__(256) logits_tma(const float* __restrict__ b_log,
                                                  float* __restrict__ out){
    extern __shared__ __align__(128) char smem[];
    const uint32_t sb = smem_u32(smem);
    const uint32_t mb0 = sb, mb1 = sb + 8;
    const uint32_t Abase = sb + 128;
    const uint32_t Bbase = sb + 128 + 32768;
    const int nt = blockIdx.x, mt = blockIdx.y;
    const int tid = threadIdx.x, lane = tid&31, wid = tid>>5;
    const int warp_m = wid>>1, warp_n = wid&1;

    if (tid==0){ MBARRIER_INIT(mb0,1); MBARRIER_INIT(mb1,1); }
    FENCE_ASYNC_SHARED();
    __syncthreads();

    float acc[2][8][4];
    #pragma unroll
    for (int a=0;a<2;a++) for (int b=0;b<8;b++) for (int q=0;q<4;q++) acc[a][b][q]=0.f;

    auto issue = [&](int chunk, int buf){
        uint32_t m_ = buf ? mb1 : mb0;
        MBARRIER_EXPECT_TX(m_, 32768u);
        BULKCP(Abase + buf*16384, g_states_h + (size_t)(mt*8+chunk)*8192, 16384u, m_);
        BULKCP(Bbase + buf*16384, g_Wlogh    + (size_t)(nt*8+chunk)*8192, 16384u, m_);
    };
    if (tid==0){ issue(0,0); issue(1,1); }

    int ph0=0, ph1=0;
    #pragma unroll 1
    for (int c=0; c<8; c++){
        const int buf = c&1;
        if (buf==0){ MBARRIER_WAIT_PARITY(mb0, ph0); ph0^=1; }
        else       { MBARRIER_WAIT_PARITY(mb1, ph1); ph1^=1; }
        const uint32_t bA = Abase + buf*16384, bB = Bbase + buf*16384;
        #pragma unroll
        for (int ks=0; ks<4; ks++){
            uint32_t af[2][4];
            #pragma unroll
            for (int mtt=0; mtt<2; mtt++){
                int row = warp_m*32 + mtt*16 + (lane&15);
                int colb = (ks*16 + ((lane>>4)<<3))*2;
                ldmx4(af[mtt][0], af[mtt][1], af[mtt][2], af[mtt][3],
                      bA + SW128(row*128 + colb));
            }
            uint32_t bf[8][2];
            #pragma unroll
            for (int ntp=0; ntp<4; ntp++){
                int n = warp_n*64 + ntp*16 + ((lane>>4)<<3) + (lane&7);
                int kb = (ks*16 + ((lane&8)?8:0))*2;
                uint32_t r0,r1,r2,r3;
                ldmx4(r0, r1, r2, r3, bB + SW128(n*128 + kb));
                bf[2*ntp][0]=r0; bf[2*ntp][1]=r1; bf[2*ntp+1][0]=r2; bf[2*ntp+1][1]=r3;
            }
            #pragma unroll
            for (int mtt=0; mtt<2; mtt++)
                #pragma unroll
                for (int ntt=0; ntt<8; ntt++)
                    mma16816(acc[mtt][ntt], af[mtt][0], af[mtt][1], af[mtt][2], af[mtt][3],
                             bf[ntt][0], bf[ntt][1]);
        }
        __syncthreads();
        if (c+2 < 8 && tid==0) issue(c+2, buf);
    }

    const int m0 = mt*128, n0 = nt*128;
    #pragma unroll
    for (int mtt=0; mtt<2; mtt++){
        int r0 = warp_m*32 + mtt*16 + (lane>>2);
        #pragma unroll
        for (int h8=0; h8<2; h8++){
            int m = m0 + r0 + h8*8;
            #pragma unroll
            for (int ntt=0; ntt<8; ntt++){
                int col = n0 + warp_n*64 + ntt*8 + (lane&3)*2;
                out[(size_t)m*VOUT + col]   = acc[mtt][ntt][h8*2+0] + b_log[col];
                out[(size_t)m*VOUT + col+1] = acc[mtt][ntt][h8*2+1] + b_log[col+1];
            }
        }
    }
}

// ===================== launch =====================
extern "C" void kernel_launch(void* const* d_in, const int* in_sizes, int n_in,
                              void* d_out, int out_size){
    const int*   x      = (const int*)  d_in[0];
    const int*   y      = (const int*)  d_in[2];
    const float* emb_in = (const float*)d_in[4];
    const float* emb_out= (const float*)d_in[5];
    const float* Wih_f  = (const float*)d_in[6];
    const float* Whh_f  = (const float*)d_in[7];
    const float* b_f    = (const float*)d_in[8];
    const float* Wih_b  = (const float*)d_in[9];
    const float* Whh_b  = (const float*)d_in[10];
    const float* b_b    = (const float*)d_in[11];
    const float* Wx     = (const float*)d_in[12];
    const float* Ws     = (const float*)d_in[13];
    const float* b_cell = (const float*)d_in[14];
    const float* W_log  = (const float*)d_in[15];
    const float* b_log  = (const float*)d_in[16];
    float* out = (float*)d_out;

    float *p_x_emb, *p_zxe, *p_zx_h, *p_zx_y, *p_bcp;
    __half *p_y_embh, *p_h_allh, *p_Wxh;
    cudaGetSymbolAddress((void**)&p_x_emb,    g_x_emb);
    cudaGetSymbolAddress((void**)&p_y_embh,   g_y_embh);
    cudaGetSymbolAddress((void**)&p_zxe,      g_zxe);
    cudaGetSymbolAddress((void**)&p_h_allh,   g_h_allh);
    cudaGetSymbolAddress((void**)&p_zx_h,     g_zx_h);
    cudaGetSymbolAddress((void**)&p_zx_y,     g_zx_y);
    cudaGetSymbolAddress((void**)&p_Wxh,      g_Wxh);
    cudaGetSymbolAddress((void**)&p_bcp,      g_bcp);

    cudaFuncSetAttribute(diag_fused, cudaFuncAttributeMaxDynamicSharedMemorySize, D_SMEM_TOT);
    cudaFuncSetAttribute(logits_tma, cudaFuncAttributeMaxDynamicSharedMemorySize, L_SMEM_TOT);

    init_zero_kernel<<<512,256>>>();
    embed_kernel<<<LIN*BSZ,EMB>>>(x, y, emb_in, emb_out);

    // weight conversions
    conv_tr_ws_kernel<<<dim3(NG5/32, (2*DD)/32),         dim3(32,8)>>>(Ws);
    conv_tr_perm_kernel<<<dim3(NG5/32, (2*DENC+EMB)/32), dim3(32,8)>>>(Wx, p_Wxh, 2*DENC+EMB, NG5);
    conv_tr_wlog_kernel<<<dim3(VOUT/32, DD/32),          dim3(32,8)>>>(W_log);
    bias_perm_kernel<<<NG5/256,256>>>(b_cell);

    // zx_y = y_emb @ Wx[512:768]^T + b_cell (permc cols)
    hmma_nt_async<<<dim3(20,16),256>>>(p_y_embh, EMB, p_Wxh + 2*DENC, 2*DENC+EMB,
                                       p_zx_y, NG5, p_bcp, EMB);

    // encoder input projections (fp32, perm4 output)
    gemm_nt_perm4<<<dim3(16,64),128>>>(p_x_emb, EMB, Wih_f, EMB, p_zxe,             NG4, b_f, EMB);
    gemm_nt_perm4<<<dim3(16,64),128>>>(p_x_emb, EMB, Wih_b, EMB, p_zxe+LIN*BSZ*NG4, NG4, b_b, EMB);

    // fused encoder recurrence
    for (int t=0; t<LIN; t++)
        enc_step_fused<<<dim3(16,2,2),128>>>(Whh_f, Whh_b, t);

    // zx_h = h_all @ Wx[0:512]^T (permc cols)
    hmma_nt_async<<<dim3(20,16),256>>>(p_h_allh, 2*DENC, p_Wxh, 2*DENC+EMB,
                                       p_zx_h, NG5, nullptr, 2*DENC);

    // 2D-LSTM wavefront: bulk-TMA fused kernel with ping-pong state buffers
    for (int d=0; d<LIN+LOUT-1; d++){
        int lo = d-31; if (lo<0) lo=0;
        int hi = d<31 ? d : 31;
        int nc = hi - lo + 1;
        int npair = (nc + 1) >> 1;
        diag_fused<<<dim3(16,npair),256,D_SMEM_TOT>>>(d);
    }

    // logits (bulk-TMA)
    logits_tma<<<dim3(250,16),256,L_SMEM_TOT>>>(b_log, out);
}